// round 1
// baseline (speedup 1.0000x reference)
#include <cuda_runtime.h>
#include <math.h>

#define S    2048
#define HID  2048
#define NH   16
#define HD   128
#define DC   256      // concatenated per-head dim (mu 128 + sigma 128)

#define BM 128
#define BN 128
#define BK 8

// ---------------- scratch (static device globals; no allocation) ----------------
__device__ float g_qcat[NH * S * DC];        // [H][S][256]  (q_mu roped | sig_q)
__device__ float g_kcat[NH * S * DC];        // [H][S][256]  (k_mu roped | sig_k)
__device__ float g_vcat[NH * S * DC];        // [H][S][256]  (v_mu | v_ls)
__device__ float g_P[NH * S * S];            // [H][S][S] logits -> probs (256MB)
__device__ float g_omu[S * HID];             // [S][HID]
__device__ float g_ols[S * HID];             // [S][HID]
__device__ float g_kn[NH * S];               // [H][S] key norm terms

enum { M_PLAIN = 0, M_CAT = 1, M_CATEXP = 2, M_LOGIT = 3 };

// ---------------- generic SGEMM: C = A(MxK, row) * B(NxK, row)^T ----------------
// 128x128 tile, 8x8 per thread, 256 threads. Epilogue selected by MODE.
template <int MODE>
__global__ __launch_bounds__(256)
void gemm_nt(const float* __restrict__ Ag, const float* __restrict__ Bg,
             float* __restrict__ Cg,
             int M, int N, int K,
             long long sA, long long sB, long long sC,
             const float* __restrict__ knB, const float* __restrict__ tau,
             int catOff)
{
    const float* A = Ag + (size_t)blockIdx.z * (size_t)sA;
    const float* B = Bg + (size_t)blockIdx.z * (size_t)sB;
    float*       C = Cg + (size_t)blockIdx.z * (size_t)sC;

    __shared__ float As[BK][BM];
    __shared__ float Bs[BK][BN];

    const int tid = threadIdx.x;
    const int tx  = tid & 15;
    const int ty  = tid >> 4;

    const int lrow = tid >> 1;           // 0..127
    const int lcol = (tid & 1) << 2;     // 0 or 4

    const float* Ald = A + (size_t)(blockIdx.y * BM + lrow) * K + lcol;
    const float* Bld = B + (size_t)(blockIdx.x * BN + lrow) * K + lcol;

    float acc[8][8] = {};

    for (int k0 = 0; k0 < K; k0 += BK) {
        float4 av = *(const float4*)(Ald + k0);
        float4 bv = *(const float4*)(Bld + k0);
        As[lcol + 0][lrow] = av.x; As[lcol + 1][lrow] = av.y;
        As[lcol + 2][lrow] = av.z; As[lcol + 3][lrow] = av.w;
        Bs[lcol + 0][lrow] = bv.x; Bs[lcol + 1][lrow] = bv.y;
        Bs[lcol + 2][lrow] = bv.z; Bs[lcol + 3][lrow] = bv.w;
        __syncthreads();
#pragma unroll
        for (int kk = 0; kk < BK; kk++) {
            float4 a0 = *(const float4*)&As[kk][ty * 4];
            float4 a1 = *(const float4*)&As[kk][64 + ty * 4];
            float4 b0 = *(const float4*)&Bs[kk][tx * 4];
            float4 b1 = *(const float4*)&Bs[kk][64 + tx * 4];
            float ar[8] = {a0.x, a0.y, a0.z, a0.w, a1.x, a1.y, a1.z, a1.w};
            float br[8] = {b0.x, b0.y, b0.z, b0.w, b1.x, b1.y, b1.z, b1.w};
#pragma unroll
            for (int i = 0; i < 8; i++)
#pragma unroll
                for (int j = 0; j < 8; j++)
                    acc[i][j] = fmaf(ar[i], br[j], acc[i][j]);
        }
        __syncthreads();
    }

    float inv_den = 1.0f;
    const float* knh = nullptr;
    if (MODE == M_LOGIT) {
        inv_den = 1.0f / (fabsf(tau[0]) + 1e-6f);
        knh = knB + (size_t)blockIdx.z * N;
    }

#pragma unroll
    for (int i = 0; i < 8; i++) {
        int gr = blockIdx.y * BM + ((i < 4) ? ty * 4 + i : 64 + ty * 4 + (i - 4));
#pragma unroll
        for (int j = 0; j < 8; j++) {
            int gc = blockIdx.x * BN + ((j < 4) ? tx * 4 + j : 64 + tx * 4 + (j - 4));
            float v = acc[i][j];
            if (MODE == M_PLAIN) {
                C[(size_t)gr * N + gc] = v;
            } else if (MODE == M_CAT) {
                C[(((size_t)(gc >> 7)) * S + gr) * DC + (gc & 127) + catOff] = v;
            } else if (MODE == M_CATEXP) {
                C[(((size_t)(gc >> 7)) * S + gr) * DC + (gc & 127) + catOff] = expf(0.5f * v);
            } else { // M_LOGIT
                C[(size_t)gr * N + gc] = (2.0f * v - knh[gc]) * inv_den;
            }
        }
    }
}

// ---------------- PV GEMM: O = P(MxK, row) * V(KxN, row), split epilogue --------
__global__ __launch_bounds__(256)
void gemm_nn_split(const float* __restrict__ Pg, const float* __restrict__ Vg,
                   float* __restrict__ Omu, float* __restrict__ Ols,
                   int M, int N, int K)
{
    const int h = blockIdx.z;
    const float* A = Pg + (size_t)h * S * S;
    const float* B = Vg + (size_t)h * S * DC;

    __shared__ float As[BK][BM];
    __shared__ float Bs[BK][BN];

    const int tid = threadIdx.x;
    const int tx  = tid & 15;
    const int ty  = tid >> 4;

    const int larow = tid >> 1;
    const int lacol = (tid & 1) << 2;
    const int lbrow = tid >> 5;          // 0..7
    const int lbcol = (tid & 31) << 2;   // 0..124

    const float* Ald = A + (size_t)(blockIdx.y * BM + larow) * K + lacol;
    const float* Bld = B + (size_t)lbrow * N + blockIdx.x * BN + lbcol;

    float acc[8][8] = {};

    for (int k0 = 0; k0 < K; k0 += BK) {
        float4 av = *(const float4*)(Ald + k0);
        float4 bv = *(const float4*)(Bld + (size_t)k0 * N);
        As[lacol + 0][larow] = av.x; As[lacol + 1][larow] = av.y;
        As[lacol + 2][larow] = av.z; As[lacol + 3][larow] = av.w;
        *(float4*)&Bs[lbrow][lbcol] = bv;
        __syncthreads();
#pragma unroll
        for (int kk = 0; kk < BK; kk++) {
            float4 a0 = *(const float4*)&As[kk][ty * 4];
            float4 a1 = *(const float4*)&As[kk][64 + ty * 4];
            float4 b0 = *(const float4*)&Bs[kk][tx * 4];
            float4 b1 = *(const float4*)&Bs[kk][64 + tx * 4];
            float ar[8] = {a0.x, a0.y, a0.z, a0.w, a1.x, a1.y, a1.z, a1.w};
            float br[8] = {b0.x, b0.y, b0.z, b0.w, b1.x, b1.y, b1.z, b1.w};
#pragma unroll
            for (int i = 0; i < 8; i++)
#pragma unroll
                for (int j = 0; j < 8; j++)
                    acc[i][j] = fmaf(ar[i], br[j], acc[i][j]);
        }
        __syncthreads();
    }

#pragma unroll
    for (int i = 0; i < 8; i++) {
        int gr = blockIdx.y * BM + ((i < 4) ? ty * 4 + i : 64 + ty * 4 + (i - 4));
#pragma unroll
        for (int j = 0; j < 8; j++) {
            int gc = blockIdx.x * BN + ((j < 4) ? tx * 4 + j : 64 + tx * 4 + (j - 4));
            float v = acc[i][j];
            if (gc < HD) Omu[(size_t)gr * HID + h * HD + gc] = v;
            else         Ols[(size_t)gr * HID + h * HD + (gc - HD)] = v;
        }
    }
}

// ---------------- RoPE in-place on first 128 dims of qcat/kcat ------------------
__global__ void rope_kernel(float* __restrict__ qcat, float* __restrict__ kcat,
                            const float* __restrict__ cosp, const float* __restrict__ sinp)
{
    int idx = blockIdx.x * blockDim.x + threadIdx.x;   // NH*S*64 = 2^21 threads
    int d = idx & 63;
    int s = (idx >> 6) & (S - 1);
    int h = idx >> 17;
    float c1 = cosp[s * HD + d],      s1 = sinp[s * HD + d];
    float c2 = cosp[s * HD + d + 64], s2 = sinp[s * HD + d + 64];
    size_t base = ((size_t)h * S + s) * DC;
    float q1 = qcat[base + d], q2 = qcat[base + d + 64];
    qcat[base + d]      = q1 * c1 - q2 * s1;
    qcat[base + d + 64] = q2 * c2 + q1 * s2;
    float k1 = kcat[base + d], k2 = kcat[base + d + 64];
    kcat[base + d]      = k1 * c1 - k2 * s1;
    kcat[base + d + 64] = k2 * c2 + k1 * s2;
}

// ---------------- key norms: kn[h*S+s] = sum_{d<256} kcat[h][s][d]^2 ------------
__global__ void kn_kernel(const float* __restrict__ kcat, float* __restrict__ kn)
{
    int gwarp = (blockIdx.x * blockDim.x + threadIdx.x) >> 5;   // row index h*S+s
    int lane  = threadIdx.x & 31;
    const float4* p = (const float4*)(kcat + (size_t)gwarp * DC);
    float acc = 0.f;
#pragma unroll
    for (int i = lane; i < 64; i += 32) {
        float4 v = p[i];
        acc += v.x * v.x + v.y * v.y + v.z * v.z + v.w * v.w;
    }
#pragma unroll
    for (int o = 16; o; o >>= 1) acc += __shfl_xor_sync(0xffffffffu, acc, o);
    if (lane == 0) kn[gwarp] = acc;
}

// ---------------- row softmax on P (in place), one block per row ----------------
__global__ void softmax_rows(float* __restrict__ Pg)
{
    float* p = Pg + (size_t)blockIdx.x * S;
    int tid = threadIdx.x;           // 256 threads, 8 elems each
    float v[8];
    float m = -1e30f;
#pragma unroll
    for (int i = 0; i < 8; i++) { v[i] = p[tid + (i << 8)]; m = fmaxf(m, v[i]); }

    __shared__ float redm[8];
#pragma unroll
    for (int o = 16; o; o >>= 1) m = fmaxf(m, __shfl_xor_sync(0xffffffffu, m, o));
    if ((tid & 31) == 0) redm[tid >> 5] = m;
    __syncthreads();
    if (tid < 32) {
        float t = (tid < 8) ? redm[tid] : -1e30f;
#pragma unroll
        for (int o = 4; o; o >>= 1) t = fmaxf(t, __shfl_xor_sync(0xffffffffu, t, o));
        if (tid == 0) redm[0] = t;
    }
    __syncthreads();
    m = redm[0];

    float s = 0.f;
#pragma unroll
    for (int i = 0; i < 8; i++) { v[i] = __expf(v[i] - m); s += v[i]; }

    __shared__ float reds[8];
#pragma unroll
    for (int o = 16; o; o >>= 1) s += __shfl_xor_sync(0xffffffffu, s, o);
    if ((tid & 31) == 0) reds[tid >> 5] = s;
    __syncthreads();
    if (tid < 32) {
        float t = (tid < 8) ? reds[tid] : 0.f;
#pragma unroll
        for (int o = 4; o; o >>= 1) t += __shfl_xor_sync(0xffffffffu, t, o);
        if (tid == 0) reds[0] = t;
    }
    __syncthreads();
    float inv = 1.f / reds[0];
#pragma unroll
    for (int i = 0; i < 8; i++) p[tid + (i << 8)] = v[i] * inv;
}

// ---------------- launch -------------------------------------------------------
extern "C" void kernel_launch(void* const* d_in, const int* in_sizes, int n_in,
                              void* d_out, int out_size)
{
    const float* xmu  = (const float*)d_in[0];
    const float* xls  = (const float*)d_in[1];
    const float* cosp = (const float*)d_in[2];
    const float* sinp = (const float*)d_in[3];
    const float* Wqm  = (const float*)d_in[4];
    const float* Wkm  = (const float*)d_in[5];
    const float* Wvm  = (const float*)d_in[6];
    const float* Wom  = (const float*)d_in[7];
    const float* Wqs  = (const float*)d_in[8];
    const float* Wks  = (const float*)d_in[9];
    const float* Wvs  = (const float*)d_in[10];
    const float* Wos  = (const float*)d_in[11];
    const float* tau  = (const float*)d_in[12];
    float* out = (float*)d_out;

    float *qcat, *kcat, *vcat, *P, *omu, *ols, *kn;
    cudaGetSymbolAddress((void**)&qcat, g_qcat);
    cudaGetSymbolAddress((void**)&kcat, g_kcat);
    cudaGetSymbolAddress((void**)&vcat, g_vcat);
    cudaGetSymbolAddress((void**)&P,    g_P);
    cudaGetSymbolAddress((void**)&omu,  g_omu);
    cudaGetSymbolAddress((void**)&ols,  g_ols);
    cudaGetSymbolAddress((void**)&kn,   g_kn);

    dim3 blk(256);

    // 1) six input projections with fused scatter/exp epilogues
    dim3 gproj(HID / BN, S / BM, 1);
    gemm_nt<M_CAT   ><<<gproj, blk>>>(xmu, Wqm, qcat, S, HID, HID, 0, 0, 0, nullptr, nullptr, 0);
    gemm_nt<M_CAT   ><<<gproj, blk>>>(xmu, Wkm, kcat, S, HID, HID, 0, 0, 0, nullptr, nullptr, 0);
    gemm_nt<M_CAT   ><<<gproj, blk>>>(xmu, Wvm, vcat, S, HID, HID, 0, 0, 0, nullptr, nullptr, 0);
    gemm_nt<M_CATEXP><<<gproj, blk>>>(xls, Wqs, qcat, S, HID, HID, 0, 0, 0, nullptr, nullptr, HD);
    gemm_nt<M_CATEXP><<<gproj, blk>>>(xls, Wks, kcat, S, HID, HID, 0, 0, 0, nullptr, nullptr, HD);
    gemm_nt<M_CAT   ><<<gproj, blk>>>(xls, Wvs, vcat, S, HID, HID, 0, 0, 0, nullptr, nullptr, HD);

    // 2) RoPE on q_mu / k_mu halves
    rope_kernel<<<(NH * S * 64) / 256, 256>>>(qcat, kcat, cosp, sinp);

    // 3) key norm terms
    kn_kernel<<<(NH * S) / 8, 256>>>(kcat, kn);

    // 4) batched logit GEMM: P = (2*Qcat·Kcat^T - kn)/(|tau|+eps)
    dim3 glog(S / BN, S / BM, NH);
    gemm_nt<M_LOGIT><<<glog, blk>>>(qcat, kcat, P, S, S, DC,
                                    (long long)S * DC, (long long)S * DC,
                                    (long long)S * S, kn, tau, 0);

    // 5) softmax rows
    softmax_rows<<<NH * S, 256>>>(P);

    // 6) batched PV GEMM with split epilogue
    dim3 gpv(DC / BN, S / BM, NH);
    gemm_nn_split<<<gpv, blk>>>(P, vcat, omu, ols, S, DC, S);

    // 7) output projections
    dim3 gout(HID / BN, S / BM, 1);
    gemm_nt<M_PLAIN><<<gout, blk>>>(omu, Wom, out,                  S, HID, HID, 0, 0, 0, nullptr, nullptr, 0);
    gemm_nt<M_PLAIN><<<gout, blk>>>(ols, Wos, out + (size_t)S * HID, S, HID, HID, 0, 0, 0, nullptr, nullptr, 0);
}

// round 2
// speedup vs baseline: 1.0002x; 1.0002x over previous
#include <cuda_runtime.h>
#include <math.h>

#define S    2048
#define HID  2048
#define NH   16
#define HD   128
#define DC   256      // concatenated per-head dim (mu 128 + sigma 128)

#define BM 128
#define BN 128
#define BK 8

// ---------------- scratch (static device globals; no allocation) ----------------
__device__ float g_qcat[NH * S * DC];        // [H][S][256]  (q_mu roped | sig_q)
__device__ float g_kcat[NH * S * DC];        // [H][S][256]  (k_mu roped | sig_k)
__device__ float g_vcat[NH * S * DC];        // [H][S][256]  (v_mu | v_ls)
__device__ float g_P[NH * S * S];            // [H][S][S] logits -> probs (256MB)
__device__ float g_omu[S * HID];             // [S][HID]
__device__ float g_ols[S * HID];             // [S][HID]
__device__ float g_kn[NH * S];               // [H][S] key norm terms

enum { M_PLAIN = 0, M_CAT = 1, M_CATEXP = 2, M_LOGIT = 3 };

// ---------------- generic SGEMM: C = A(MxK, row) * B(NxK, row)^T ----------------
// 128x128 tile, 8x8 per thread, 256 threads. Epilogue selected by MODE.
template <int MODE>
__global__ __launch_bounds__(256)
void gemm_nt(const float* __restrict__ Ag, const float* __restrict__ Bg,
             float* __restrict__ Cg,
             int M, int N, int K,
             long long sA, long long sB, long long sC,
             const float* __restrict__ knB, const float* __restrict__ tau,
             int catOff)
{
    const float* A = Ag + (size_t)blockIdx.z * (size_t)sA;
    const float* B = Bg + (size_t)blockIdx.z * (size_t)sB;
    float*       C = Cg + (size_t)blockIdx.z * (size_t)sC;

    __shared__ float As[BK][BM];
    __shared__ float Bs[BK][BN];

    const int tid = threadIdx.x;
    const int tx  = tid & 15;
    const int ty  = tid >> 4;

    const int lrow = tid >> 1;           // 0..127
    const int lcol = (tid & 1) << 2;     // 0 or 4

    const float* Ald = A + (size_t)(blockIdx.y * BM + lrow) * K + lcol;
    const float* Bld = B + (size_t)(blockIdx.x * BN + lrow) * K + lcol;

    float acc[8][8] = {};

    for (int k0 = 0; k0 < K; k0 += BK) {
        float4 av = *(const float4*)(Ald + k0);
        float4 bv = *(const float4*)(Bld + k0);
        As[lcol + 0][lrow] = av.x; As[lcol + 1][lrow] = av.y;
        As[lcol + 2][lrow] = av.z; As[lcol + 3][lrow] = av.w;
        Bs[lcol + 0][lrow] = bv.x; Bs[lcol + 1][lrow] = bv.y;
        Bs[lcol + 2][lrow] = bv.z; Bs[lcol + 3][lrow] = bv.w;
        __syncthreads();
#pragma unroll
        for (int kk = 0; kk < BK; kk++) {
            float4 a0 = *(const float4*)&As[kk][ty * 4];
            float4 a1 = *(const float4*)&As[kk][64 + ty * 4];
            float4 b0 = *(const float4*)&Bs[kk][tx * 4];
            float4 b1 = *(const float4*)&Bs[kk][64 + tx * 4];
            float ar[8] = {a0.x, a0.y, a0.z, a0.w, a1.x, a1.y, a1.z, a1.w};
            float br[8] = {b0.x, b0.y, b0.z, b0.w, b1.x, b1.y, b1.z, b1.w};
#pragma unroll
            for (int i = 0; i < 8; i++)
#pragma unroll
                for (int j = 0; j < 8; j++)
                    acc[i][j] = fmaf(ar[i], br[j], acc[i][j]);
        }
        __syncthreads();
    }

    float inv_den = 1.0f;
    const float* knh = nullptr;
    if (MODE == M_LOGIT) {
        inv_den = 1.0f / (fabsf(tau[0]) + 1e-6f);
        knh = knB + (size_t)blockIdx.z * N;
    }

#pragma unroll
    for (int i = 0; i < 8; i++) {
        int gr = blockIdx.y * BM + ((i < 4) ? ty * 4 + i : 64 + ty * 4 + (i - 4));
#pragma unroll
        for (int j = 0; j < 8; j++) {
            int gc = blockIdx.x * BN + ((j < 4) ? tx * 4 + j : 64 + tx * 4 + (j - 4));
            float v = acc[i][j];
            if (MODE == M_PLAIN) {
                C[(size_t)gr * N + gc] = v;
            } else if (MODE == M_CAT) {
                C[(((size_t)(gc >> 7)) * S + gr) * DC + (gc & 127) + catOff] = v;
            } else if (MODE == M_CATEXP) {
                C[(((size_t)(gc >> 7)) * S + gr) * DC + (gc & 127) + catOff] = expf(0.5f * v);
            } else { // M_LOGIT
                C[(size_t)gr * N + gc] = (2.0f * v - knh[gc]) * inv_den;
            }
        }
    }
}

// ---------------- PV GEMM: O = P(MxK, row) * V(KxN, row), split epilogue --------
__global__ __launch_bounds__(256)
void gemm_nn_split(const float* __restrict__ Pg, const float* __restrict__ Vg,
                   float* __restrict__ Omu, float* __restrict__ Ols,
                   int M, int N, int K)
{
    const int h = blockIdx.z;
    const float* A = Pg + (size_t)h * S * S;
    const float* B = Vg + (size_t)h * S * DC;

    __shared__ float As[BK][BM];
    __shared__ float Bs[BK][BN];

    const int tid = threadIdx.x;
    const int tx  = tid & 15;
    const int ty  = tid >> 4;

    const int larow = tid >> 1;
    const int lacol = (tid & 1) << 2;
    const int lbrow = tid >> 5;          // 0..7
    const int lbcol = (tid & 31) << 2;   // 0..124

    const float* Ald = A + (size_t)(blockIdx.y * BM + larow) * K + lacol;
    const float* Bld = B + (size_t)lbrow * N + blockIdx.x * BN + lbcol;

    float acc[8][8] = {};

    for (int k0 = 0; k0 < K; k0 += BK) {
        float4 av = *(const float4*)(Ald + k0);
        float4 bv = *(const float4*)(Bld + (size_t)k0 * N);
        As[lacol + 0][larow] = av.x; As[lacol + 1][larow] = av.y;
        As[lacol + 2][larow] = av.z; As[lacol + 3][larow] = av.w;
        *(float4*)&Bs[lbrow][lbcol] = bv;
        __syncthreads();
#pragma unroll
        for (int kk = 0; kk < BK; kk++) {
            float4 a0 = *(const float4*)&As[kk][ty * 4];
            float4 a1 = *(const float4*)&As[kk][64 + ty * 4];
            float4 b0 = *(const float4*)&Bs[kk][tx * 4];
            float4 b1 = *(const float4*)&Bs[kk][64 + tx * 4];
            float ar[8] = {a0.x, a0.y, a0.z, a0.w, a1.x, a1.y, a1.z, a1.w};
            float br[8] = {b0.x, b0.y, b0.z, b0.w, b1.x, b1.y, b1.z, b1.w};
#pragma unroll
            for (int i = 0; i < 8; i++)
#pragma unroll
                for (int j = 0; j < 8; j++)
                    acc[i][j] = fmaf(ar[i], br[j], acc[i][j]);
        }
        __syncthreads();
    }

#pragma unroll
    for (int i = 0; i < 8; i++) {
        int gr = blockIdx.y * BM + ((i < 4) ? ty * 4 + i : 64 + ty * 4 + (i - 4));
#pragma unroll
        for (int j = 0; j < 8; j++) {
            int gc = blockIdx.x * BN + ((j < 4) ? tx * 4 + j : 64 + tx * 4 + (j - 4));
            float v = acc[i][j];
            if (gc < HD) Omu[(size_t)gr * HID + h * HD + gc] = v;
            else         Ols[(size_t)gr * HID + h * HD + (gc - HD)] = v;
        }
    }
}

// ---------------- RoPE in-place on first 128 dims of qcat/kcat ------------------
__global__ void rope_kernel(float* __restrict__ qcat, float* __restrict__ kcat,
                            const float* __restrict__ cosp, const float* __restrict__ sinp)
{
    int idx = blockIdx.x * blockDim.x + threadIdx.x;   // NH*S*64 = 2^21 threads
    int d = idx & 63;
    int s = (idx >> 6) & (S - 1);
    int h = idx >> 17;
    float c1 = cosp[s * HD + d],      s1 = sinp[s * HD + d];
    float c2 = cosp[s * HD + d + 64], s2 = sinp[s * HD + d + 64];
    size_t base = ((size_t)h * S + s) * DC;
    float q1 = qcat[base + d], q2 = qcat[base + d + 64];
    qcat[base + d]      = q1 * c1 - q2 * s1;
    qcat[base + d + 64] = q2 * c2 + q1 * s2;
    float k1 = kcat[base + d], k2 = kcat[base + d + 64];
    kcat[base + d]      = k1 * c1 - k2 * s1;
    kcat[base + d + 64] = k2 * c2 + k1 * s2;
}

// ---------------- key norms: kn[h*S+s] = sum_{d<256} kcat[h][s][d]^2 ------------
__global__ void kn_kernel(const float* __restrict__ kcat, float* __restrict__ kn)
{
    int gwarp = (blockIdx.x * blockDim.x + threadIdx.x) >> 5;   // row index h*S+s
    int lane  = threadIdx.x & 31;
    const float4* p = (const float4*)(kcat + (size_t)gwarp * DC);
    float acc = 0.f;
#pragma unroll
    for (int i = lane; i < 64; i += 32) {
        float4 v = p[i];
        acc += v.x * v.x + v.y * v.y + v.z * v.z + v.w * v.w;
    }
#pragma unroll
    for (int o = 16; o; o >>= 1) acc += __shfl_xor_sync(0xffffffffu, acc, o);
    if (lane == 0) kn[gwarp] = acc;
}

// ---------------- row softmax on P (in place), one block per row ----------------
__global__ void softmax_rows(float* __restrict__ Pg)
{
    float* p = Pg + (size_t)blockIdx.x * S;
    int tid = threadIdx.x;           // 256 threads, 8 elems each
    float v[8];
    float m = -1e30f;
#pragma unroll
    for (int i = 0; i < 8; i++) { v[i] = p[tid + (i << 8)]; m = fmaxf(m, v[i]); }

    __shared__ float redm[8];
#pragma unroll
    for (int o = 16; o; o >>= 1) m = fmaxf(m, __shfl_xor_sync(0xffffffffu, m, o));
    if ((tid & 31) == 0) redm[tid >> 5] = m;
    __syncthreads();
    if (tid < 32) {
        float t = (tid < 8) ? redm[tid] : -1e30f;
#pragma unroll
        for (int o = 4; o; o >>= 1) t = fmaxf(t, __shfl_xor_sync(0xffffffffu, t, o));
        if (tid == 0) redm[0] = t;
    }
    __syncthreads();
    m = redm[0];

    float s = 0.f;
#pragma unroll
    for (int i = 0; i < 8; i++) { v[i] = __expf(v[i] - m); s += v[i]; }

    __shared__ float reds[8];
#pragma unroll
    for (int o = 16; o; o >>= 1) s += __shfl_xor_sync(0xffffffffu, s, o);
    if ((tid & 31) == 0) reds[tid >> 5] = s;
    __syncthreads();
    if (tid < 32) {
        float t = (tid < 8) ? reds[tid] : 0.f;
#pragma unroll
        for (int o = 4; o; o >>= 1) t += __shfl_xor_sync(0xffffffffu, t, o);
        if (tid == 0) reds[0] = t;
    }
    __syncthreads();
    float inv = 1.f / reds[0];
#pragma unroll
    for (int i = 0; i < 8; i++) p[tid + (i << 8)] = v[i] * inv;
}

// ---------------- launch -------------------------------------------------------
extern "C" void kernel_launch(void* const* d_in, const int* in_sizes, int n_in,
                              void* d_out, int out_size)
{
    const float* xmu  = (const float*)d_in[0];
    const float* xls  = (const float*)d_in[1];
    const float* cosp = (const float*)d_in[2];
    const float* sinp = (const float*)d_in[3];
    const float* Wqm  = (const float*)d_in[4];
    const float* Wkm  = (const float*)d_in[5];
    const float* Wvm  = (const float*)d_in[6];
    const float* Wom  = (const float*)d_in[7];
    const float* Wqs  = (const float*)d_in[8];
    const float* Wks  = (const float*)d_in[9];
    const float* Wvs  = (const float*)d_in[10];
    const float* Wos  = (const float*)d_in[11];
    const float* tau  = (const float*)d_in[12];
    float* out = (float*)d_out;

    float *qcat, *kcat, *vcat, *P, *omu, *ols, *kn;
    cudaGetSymbolAddress((void**)&qcat, g_qcat);
    cudaGetSymbolAddress((void**)&kcat, g_kcat);
    cudaGetSymbolAddress((void**)&vcat, g_vcat);
    cudaGetSymbolAddress((void**)&P,    g_P);
    cudaGetSymbolAddress((void**)&omu,  g_omu);
    cudaGetSymbolAddress((void**)&ols,  g_ols);
    cudaGetSymbolAddress((void**)&kn,   g_kn);

    dim3 blk(256);

    // 1) six input projections with fused scatter/exp epilogues
    dim3 gproj(HID / BN, S / BM, 1);
    gemm_nt<M_CAT   ><<<gproj, blk>>>(xmu, Wqm, qcat, S, HID, HID, 0, 0, 0, nullptr, nullptr, 0);
    gemm_nt<M_CAT   ><<<gproj, blk>>>(xmu, Wkm, kcat, S, HID, HID, 0, 0, 0, nullptr, nullptr, 0);
    gemm_nt<M_CAT   ><<<gproj, blk>>>(xmu, Wvm, vcat, S, HID, HID, 0, 0, 0, nullptr, nullptr, 0);
    gemm_nt<M_CATEXP><<<gproj, blk>>>(xls, Wqs, qcat, S, HID, HID, 0, 0, 0, nullptr, nullptr, HD);
    gemm_nt<M_CATEXP><<<gproj, blk>>>(xls, Wks, kcat, S, HID, HID, 0, 0, 0, nullptr, nullptr, HD);
    gemm_nt<M_CAT   ><<<gproj, blk>>>(xls, Wvs, vcat, S, HID, HID, 0, 0, 0, nullptr, nullptr, HD);

    // 2) RoPE on q_mu / k_mu halves
    rope_kernel<<<(NH * S * 64) / 256, 256>>>(qcat, kcat, cosp, sinp);

    // 3) key norm terms
    kn_kernel<<<(NH * S) / 8, 256>>>(kcat, kn);

    // 4) batched logit GEMM: P = (2*Qcat·Kcat^T - kn)/(|tau|+eps)
    dim3 glog(S / BN, S / BM, NH);
    gemm_nt<M_LOGIT><<<glog, blk>>>(qcat, kcat, P, S, S, DC,
                                    (long long)S * DC, (long long)S * DC,
                                    (long long)S * S, kn, tau, 0);

    // 5) softmax rows
    softmax_rows<<<NH * S, 256>>>(P);

    // 6) batched PV GEMM with split epilogue
    dim3 gpv(DC / BN, S / BM, NH);
    gemm_nn_split<<<gpv, blk>>>(P, vcat, omu, ols, S, DC, S);

    // 7) output projections
    dim3 gout(HID / BN, S / BM, 1);
    gemm_nt<M_PLAIN><<<gout, blk>>>(omu, Wom, out,                  S, HID, HID, 0, 0, 0, nullptr, nullptr, 0);
    gemm_nt<M_PLAIN><<<gout, blk>>>(ols, Wos, out + (size_t)S * HID, S, HID, HID, 0, 0, 0, nullptr, nullptr, 0);
}